// round 14
// baseline (speedup 1.0000x reference)
#include <cuda_runtime.h>

#define HH   128      // hidden dim
#define NN   2048     // points per batch
#define BB   16       // batches
#define KK1  10       // K+1 neighbors (incl. self)
#define TPB  128      // threads per block (search kernel)
#define PPB  64       // points per block = TPB/2 (2 threads per point)
#define G    32       // grid resolution per axis
#define GC   (G * G)
#define CSP  (GC + 4) // cellStart smem pad (keeps gs 16B-aligned)
#define EPSM 1e-4f    // bound margin >> max d2 rounding error (~1e-5)

// packed dual-FMA: two independent rn fp32 FMAs in one instruction (sm_10x)
#define FMA_F32X2(acc, a, w) \
    asm("fma.rn.f32x2 %0, %1, %2, %3;" : "=l"(acc) : "l"(a), "l"(w), "l"(acc))

// __device__ scratch (no cudaMalloc allowed)
__device__ __align__(16) float g_Wf[HH * 24];
__device__ float  g_bias[HH];
__device__ float4 g_sorted[BB * NN];        // (x, y, sq, packed) cell-sorted
__device__ int    g_cellStart[BB][GC + 1];
__device__ float4 g_gridInfo[BB];           // (ox, oy, invh, h)

// serpentine (boustrophedon) cell id: odd rows reversed -> consecutive ids
// are always spatially adjacent (no row-wrap discontinuity)
__device__ __forceinline__ int serpId(int x, int y) {
    return y * G + ((y & 1) ? (G - 1 - x) : x);
}

// ---------------------------------------------------------------------------
// Prep kernel: blocks 0..15 build per-batch grid; blocks 16..23 fuse weights.
// ---------------------------------------------------------------------------
__global__ __launch_bounds__(512, 1)
void prep_kernel(const float* __restrict__ x,
                 const float* __restrict__ Wconv,
                 const float* __restrict__ bconv,
                 const float* __restrict__ W1,
                 const float* __restrict__ b1,
                 const float* __restrict__ W2,
                 const float* __restrict__ b2) {
    __shared__ int   hist[GC];
    __shared__ float rmn[16][2];
    __shared__ float rmx[16][2];
    __shared__ int   wsum[16];
    __shared__ float s_info[4];

    int blk = blockIdx.x, tid = threadIdx.x;
    int lane = tid & 31, wid = tid >> 5;

    if (blk >= BB) {
        // ---- weight fusion: warp per output channel e ----
        int e = (blk - BB) * 16 + wid;
        float acc[21];
#pragma unroll
        for (int j = 0; j < 21; ++j) acc[j] = 0.f;
        for (int h = lane; h < HH; h += 32) {
            float w2 = W2[e * HH + h];
            const float* wc = Wconv + h * 20;   // Wconv[h][c][k], c stride 10
#pragma unroll
            for (int j = 0; j < 20; ++j) {
                int c = j & 1, k = j >> 1;
                acc[j] = fmaf(w2, wc[c * 10 + k], acc[j]);
            }
            acc[20] = fmaf(w2, bconv[h], acc[20]);
        }
#pragma unroll
        for (int off = 16; off; off >>= 1) {
#pragma unroll
            for (int j = 0; j < 21; ++j)
                acc[j] += __shfl_xor_sync(0xffffffffu, acc[j], off);
        }
        if (lane == 0) {
#pragma unroll
            for (int j = 0; j < 20; ++j) g_Wf[e * 24 + j] = acc[j];
            g_Wf[e * 24 + 20] = W1[e * 2 + 0];
            g_Wf[e * 24 + 21] = W1[e * 2 + 1];
            g_Wf[e * 24 + 22] = 0.f;
            g_Wf[e * 24 + 23] = 0.f;
            g_bias[e] = acc[20] + b1[e] + b2[e];
        }
        return;
    }

    // ---- grid build for batch b ----
    int b = blk;
    const float2* xb = reinterpret_cast<const float2*>(x) + (size_t)b * NN;

    float2 p[4];
#pragma unroll
    for (int i = 0; i < 4; ++i) p[i] = xb[tid + 512 * i];

    // bbox reduction
    float mnx = p[0].x, mxx = p[0].x, mny = p[0].y, mxy = p[0].y;
#pragma unroll
    for (int i = 1; i < 4; ++i) {
        mnx = fminf(mnx, p[i].x); mxx = fmaxf(mxx, p[i].x);
        mny = fminf(mny, p[i].y); mxy = fmaxf(mxy, p[i].y);
    }
#pragma unroll
    for (int off = 16; off; off >>= 1) {
        mnx = fminf(mnx, __shfl_xor_sync(~0u, mnx, off));
        mxx = fmaxf(mxx, __shfl_xor_sync(~0u, mxx, off));
        mny = fminf(mny, __shfl_xor_sync(~0u, mny, off));
        mxy = fmaxf(mxy, __shfl_xor_sync(~0u, mxy, off));
    }
    if (lane == 0) { rmn[wid][0] = mnx; rmn[wid][1] = mny;
                     rmx[wid][0] = mxx; rmx[wid][1] = mxy; }
    __syncthreads();
    if (tid == 0) {
        float a = rmn[0][0], bx = rmx[0][0], c = rmn[0][1], d = rmx[0][1];
        for (int i = 1; i < 16; ++i) {
            a = fminf(a, rmn[i][0]); bx = fmaxf(bx, rmx[i][0]);
            c = fminf(c, rmn[i][1]); d = fmaxf(d, rmx[i][1]);
        }
        float ox = a - 1e-4f, oy = c - 1e-4f;
        float range = fmaxf(bx - a, d - c) + 2e-4f;
        float h = range / (float)G;
        float invh = 1.0f / h;
        s_info[0] = ox; s_info[1] = oy; s_info[2] = invh;
        g_gridInfo[b] = make_float4(ox, oy, invh, h);
    }
    for (int i = tid; i < GC; i += 512) hist[i] = 0;
    __syncthreads();

    float ox = s_info[0], oy = s_info[1], invh = s_info[2];
    int cell[4];
#pragma unroll
    for (int i = 0; i < 4; ++i) {
        int cx = (int)((p[i].x - ox) * invh); cx = max(0, min(G - 1, cx));
        int cy = (int)((p[i].y - oy) * invh); cy = max(0, min(G - 1, cy));
        cell[i] = serpId(cx, cy);
        atomicAdd(&hist[cell[i]], 1);
    }
    __syncthreads();

    // exclusive prefix sum over GC=1024 bins (2 per thread)
    int base = tid * 2;
    int v0 = hist[base], v1 = hist[base + 1];
    int s = v0 + v1;
    int inc = s;
#pragma unroll
    for (int off = 1; off < 32; off <<= 1) {
        int n = __shfl_up_sync(~0u, inc, off);
        if (lane >= off) inc += n;
    }
    if (lane == 31) wsum[wid] = inc;
    int wex = inc - s;
    __syncthreads();
    if (wid == 0) {
        int vv = (lane < 16) ? wsum[lane] : 0;
        int orig = vv;
#pragma unroll
        for (int off = 1; off < 16; off <<= 1) {
            int n = __shfl_up_sync(~0u, vv, off);
            if (lane >= off) vv += n;
        }
        if (lane < 16) wsum[lane] = vv - orig;
    }
    __syncthreads();
    int gbase = wsum[wid] + wex;
    g_cellStart[b][base]     = gbase;
    g_cellStart[b][base + 1] = gbase + v0;
    hist[base]     = gbase;          // becomes scatter cursor
    hist[base + 1] = gbase + v0;
    if (tid == 0) g_cellStart[b][GC] = NN;
    __syncthreads();

    // scatter (order within cell arbitrary; ties resolved by packed orig idx)
#pragma unroll
    for (int i = 0; i < 4; ++i) {
        int pos = atomicAdd(&hist[cell[i]], 1);
        float sq = __fadd_rn(__fmul_rn(p[i].x, p[i].x),
                             __fmul_rn(p[i].y, p[i].y));
        int orig = tid + 512 * i;
        g_sorted[b * NN + pos] =
            make_float4(p[i].x, p[i].y, sq, __int_as_float((orig << 11) | pos));
    }
}

// ---------------------------------------------------------------------------
// Main kernel: 2 threads per point. Serpentine cell order => a warp's 16
// consecutive points are path-adjacent => WARP-UNIFORM union rect is narrow
// (no row-wrap blowup). All rect coords / spans / trip counts warp-uniform;
// divergence only on inserts. Top-10 over the rect superset is still the
// exact stable top-10 (extra candidates can only be inserted; unique u64
// keys). Per-lane stop bound: exact distance from my point to each scanned-
// rect wall (any unscanned point lies beyond a wall); grid-edge walls have
// no unseen cells. Selection key = (bits(max(d2,0))<<32)|(orig<<11|pos).
// ---------------------------------------------------------------------------
__global__ __launch_bounds__(TPB, 5)
void conv_embed_kernel(float* __restrict__ out) {
    extern __shared__ float smem[];
    float4* xs    = reinterpret_cast<float4*>(smem);          // [NN]   32 KB
    int*    cs    = reinterpret_cast<int*>(smem + NN * 4);    // [CSP]  4.1 KB
    float*  gs    = smem + NN * 4 + CSP;                      // [PPB*24] 6.1 KB
    int*    gorig = reinterpret_cast<int*>(gs + PPB * 24);    // [PPB]

    int b = blockIdx.y;
    int tid = threadIdx.x;

    // Phase 0: stage batch data
    const float4* srt = g_sorted + b * NN;
    for (int i = tid; i < NN; i += TPB) xs[i] = srt[i];
    for (int i = tid; i < GC + 1; i += TPB) cs[i] = g_cellStart[b][i];
    float4 gi = g_gridInfo[b];
    __syncthreads();

    // Phase 1: lane pair (2i,2i+1) shares point i (half-stride split)
    int half = tid & 1;
    int lp   = tid >> 1;                   // local point 0..63
    int sp   = blockIdx.x * PPB + lp;      // sorted position
    float4 me = xs[sp];
    float x0 = me.x, x1 = me.y, sqi = me.z;
    int mypacked = __float_as_int(me.w);

    float relx = x0 - gi.x;
    float rely = x1 - gi.y;
    int cx = (int)(relx * gi.z); cx = max(0, min(G - 1, cx));
    int cy = (int)(rely * gi.z); cy = max(0, min(G - 1, cy));
    float h = gi.w;

    // warp-shared rect = union of lanes' cells (narrow under serpentine order)
    int rx0 = cx, rx1 = cx, ry0 = cy, ry1 = cy;
#pragma unroll
    for (int off = 16; off; off >>= 1) {
        rx0 = min(rx0, __shfl_xor_sync(~0u, rx0, off));
        rx1 = max(rx1, __shfl_xor_sync(~0u, rx1, off));
        ry0 = min(ry0, __shfl_xor_sync(~0u, ry0, off));
        ry1 = max(ry1, __shfl_xor_sync(~0u, ry1, off));
    }

    unsigned long long lst[KK1];
#pragma unroll
    for (int s = 0; s < KK1; ++s) lst[s] = 0xFFFFFFFFFFFFFFFFULL;

    // scan cells [xa,xb] of row y (warp-uniform args); serpentine index map
    auto evalRow = [&](int y, int xa, int xb) {
        int rb = y * G;
        int lo = (y & 1) ? rb + (G - 1 - xb) : rb + xa;
        int hi = (y & 1) ? rb + (G - 1 - xa) : rb + xb;
        int q0 = cs[lo], q1 = cs[hi + 1];
        for (int q = q0 + half; q < q1; q += 2) {   // stride-2 pair split
            float4 c = xs[q];
            float dot = __fadd_rn(__fmul_rn(x0, c.x), __fmul_rn(x1, c.y));
            float d2  = __fmaf_rn(-2.0f, dot, __fadd_rn(sqi, c.z));
            d2 = fmaxf(d2, 0.0f);
            unsigned long long nk =
                ((unsigned long long)__float_as_uint(d2) << 32) |
                (unsigned)__float_as_int(c.w);
            if (nk < lst[KK1 - 1]) {
                lst[KK1 - 1] = nk;
#pragma unroll
                for (int s = KK1 - 1; s >= 1; --s) {   // branchless bubble
                    unsigned long long lo2 = lst[s] < lst[s - 1] ? lst[s] : lst[s - 1];
                    unsigned long long hi2 = lst[s] < lst[s - 1] ? lst[s - 1] : lst[s];
                    lst[s - 1] = lo2; lst[s] = hi2;
                }
            }
        }
    };

    // initial rect
    for (int iy = ry0; iy <= ry1; ++iy) evalRow(iy, rx0, rx1);

    while (true) {
        // per-lane bound: exact distance from my point to scanned-rect walls
        float bl = (rx0 > 0)     ? relx - (float)rx0 * h       : 1e9f;
        float br = (rx1 < G - 1) ? (float)(rx1 + 1) * h - relx : 1e9f;
        float bb = (ry0 > 0)     ? rely - (float)ry0 * h       : 1e9f;
        float bt = (ry1 < G - 1) ? (float)(ry1 + 1) * h - rely : 1e9f;
        float bnd = fminf(fminf(bl, br), fminf(bb, bt));
        float k9  = __uint_as_float((unsigned)(lst[KK1 - 1] >> 32)); // NaN til full
        float kmin = fminf(k9, __shfl_xor_sync(0xffffffffu, k9, 1));
        bool done_l = (bnd * bnd > kmin + EPSM);       // NaN -> false
        if (__all_sync(0xffffffffu, done_l)) break;
        if (rx0 == 0 && ry0 == 0 && rx1 == G - 1 && ry1 == G - 1) break;

        // expand rect by 1 on all sides; scan only NEW cells (all uniform)
        int nx0 = max(rx0 - 1, 0), nx1 = min(rx1 + 1, G - 1);
        int ny0 = max(ry0 - 1, 0), ny1 = min(ry1 + 1, G - 1);
        if (ny0 < ry0) evalRow(ny0, nx0, nx1);
        if (ny1 > ry1) evalRow(ny1, nx0, nx1);
        for (int iy = ry0; iy <= ry1; ++iy) {
            if (nx0 < rx0) evalRow(iy, nx0, nx0);
            if (nx1 > rx1) evalRow(iy, nx1, nx1);
        }
        rx0 = nx0; rx1 = nx1; ry0 = ny0; ry1 = ny1;
    }

    // pair merge: pull partner's sorted-10, insert with early-out (exact u64)
    unsigned long long plst[KK1];
#pragma unroll
    for (int j = 0; j < KK1; ++j)
        plst[j] = __shfl_xor_sync(0xffffffffu, lst[j], 1);
#pragma unroll
    for (int j = 0; j < KK1; ++j) {
        if (plst[j] < lst[KK1 - 1]) {
            lst[KK1 - 1] = plst[j];
#pragma unroll
            for (int s = KK1 - 1; s >= 1; --s) {
                unsigned long long lo2 = lst[s] < lst[s - 1] ? lst[s] : lst[s - 1];
                unsigned long long hi2 = lst[s] < lst[s - 1] ? lst[s - 1] : lst[s];
                lst[s - 1] = lo2; lst[s] = hi2;
            }
        } else break;                      // partner ascending -> rest bigger
    }

    // Gather in ref order (descending distance, self last): rank 9-k.
    // Both pair threads hold identical merged lists; split the writes.
    float* g = gs + lp * 24;
#pragma unroll
    for (int k2 = 0; k2 < 5; ++k2) {
        int k = half * 5 + k2;
        int pk = (int)(lst[KK1 - 1 - k] & 0xFFFFFFFFULL);
        float4 cc = xs[pk & 0x7FF];
        g[2 * k]     = cc.x;
        g[2 * k + 1] = cc.y;
    }
    if (half == 0) {
        g[20] = x0; g[21] = x1; g[22] = 0.f; g[23] = 0.f;
        gorig[lp] = mypacked >> 11;
    }
    __syncthreads();

    // Phase 2: out[orig][e] = bias[e] + sum_t g[row][t] * Wf[e][t]
    // f32x2-packed: lanes accumulate the SAME per-lane FMA sequence as the
    // scalar version (acc0..acc3 interleave) => bit-identical result.
    int e = tid;                          // 128 threads = 128 channels
    const unsigned long long* wfp =
        reinterpret_cast<const unsigned long long*>(g_Wf + e * 24);
    unsigned long long wv[12];
#pragma unroll
    for (int j = 0; j < 12; ++j) wv[j] = wfp[j];
    float biasv = g_bias[e];

    size_t outbase = (size_t)b * NN;
#pragma unroll 2
    for (int row = 0; row < PPB; ++row) {
        const ulonglong2* gv = reinterpret_cast<const ulonglong2*>(gs + row * 24);
        ulonglong2 q0 = gv[0], q1 = gv[1], q2 = gv[2];
        ulonglong2 q3 = gv[3], q4 = gv[4], q5 = gv[5];
        unsigned long long acc01 = (unsigned long long)__float_as_uint(biasv);
        unsigned long long acc23 = 0ULL;
        FMA_F32X2(acc01, q0.x, wv[0]);   // floats 0,1   -> acc0,acc1
        FMA_F32X2(acc23, q0.y, wv[1]);   // floats 2,3   -> acc2,acc3
        FMA_F32X2(acc01, q1.x, wv[2]);
        FMA_F32X2(acc23, q1.y, wv[3]);
        FMA_F32X2(acc01, q2.x, wv[4]);
        FMA_F32X2(acc23, q2.y, wv[5]);
        FMA_F32X2(acc01, q3.x, wv[6]);
        FMA_F32X2(acc23, q3.y, wv[7]);
        FMA_F32X2(acc01, q4.x, wv[8]);
        FMA_F32X2(acc23, q4.y, wv[9]);
        FMA_F32X2(acc01, q5.x, wv[10]);
        FMA_F32X2(acc23, q5.y, wv[11]);
        float acc0 = __uint_as_float((unsigned)(acc01 & 0xFFFFFFFFULL));
        float acc1 = __uint_as_float((unsigned)(acc01 >> 32));
        float acc2 = __uint_as_float((unsigned)(acc23 & 0xFFFFFFFFULL));
        float acc3 = __uint_as_float((unsigned)(acc23 >> 32));
        out[(outbase + gorig[row]) * HH + e] = (acc0 + acc1) + (acc2 + acc3);
    }
}

extern "C" void kernel_launch(void* const* d_in, const int* in_sizes, int n_in,
                              void* d_out, int out_size) {
    const float* x     = (const float*)d_in[0];  // (16,2048,2)
    const float* Wconv = (const float*)d_in[1];  // (128,2,10)
    const float* bconv = (const float*)d_in[2];  // (128,)
    const float* W1    = (const float*)d_in[3];  // (128,2)
    const float* b1    = (const float*)d_in[4];  // (128,)
    const float* W2    = (const float*)d_in[5];  // (128,128)
    const float* b2    = (const float*)d_in[6];  // (128,)
    float* out = (float*)d_out;                  // (16,2048,128) fp32

    prep_kernel<<<BB + 8, 512>>>(x, Wconv, bconv, W1, b1, W2, b2);

    size_t smem_bytes = ((size_t)NN * 4 + CSP + (size_t)PPB * 24 + PPB) * 4;
    cudaFuncSetAttribute(conv_embed_kernel,
                         cudaFuncAttributeMaxDynamicSharedMemorySize,
                         (int)smem_bytes);
    dim3 grid(NN / PPB, BB);
    conv_embed_kernel<<<grid, TPB, smem_bytes>>>(out);
}

// round 15
// speedup vs baseline: 1.3973x; 1.3973x over previous
#include <cuda_runtime.h>

#define HH   128      // hidden dim
#define NN   2048     // points per batch
#define BB   16       // batches
#define KK1  10       // K+1 neighbors (incl. self)
#define TPB  128      // threads per block (search kernel)
#define PPB  64       // points per block = TPB/2 (2 threads per point)
#define G    32       // grid resolution per axis
#define GC   (G * G)
#define CSP  (GC + 4) // cellStart smem pad (keeps gs 16B-aligned)
#define EPSM 1e-4f    // ring-bound margin >> max d2 rounding error (~1e-5)

// packed dual-FMA: two independent rn fp32 FMAs in one instruction (sm_10x)
#define FMA_F32X2(acc, a, w) \
    asm("fma.rn.f32x2 %0, %1, %2, %3;" : "=l"(acc) : "l"(a), "l"(w), "l"(acc))

// __device__ scratch (no cudaMalloc allowed)
__device__ __align__(16) float g_Wf[HH * 24];
__device__ float  g_bias[HH];
__device__ float4 g_sorted[BB * NN];        // (x, y, sq, packed) cell-sorted
__device__ int    g_cellStart[BB][GC + 1];
__device__ float4 g_gridInfo[BB];           // (ox, oy, invh, h)

// ---------------------------------------------------------------------------
// Prep kernel: blocks 0..15 build per-batch grid; blocks 16..23 fuse weights.
// ---------------------------------------------------------------------------
__global__ __launch_bounds__(512, 1)
void prep_kernel(const float* __restrict__ x,
                 const float* __restrict__ Wconv,
                 const float* __restrict__ bconv,
                 const float* __restrict__ W1,
                 const float* __restrict__ b1,
                 const float* __restrict__ W2,
                 const float* __restrict__ b2) {
    __shared__ int   hist[GC];
    __shared__ float rmn[16][2];
    __shared__ float rmx[16][2];
    __shared__ int   wsum[16];
    __shared__ float s_info[4];

    int blk = blockIdx.x, tid = threadIdx.x;
    int lane = tid & 31, wid = tid >> 5;

    if (blk >= BB) {
        // ---- weight fusion: warp per output channel e ----
        int e = (blk - BB) * 16 + wid;
        float acc[21];
#pragma unroll
        for (int j = 0; j < 21; ++j) acc[j] = 0.f;
        for (int h = lane; h < HH; h += 32) {
            float w2 = W2[e * HH + h];
            const float* wc = Wconv + h * 20;   // Wconv[h][c][k], c stride 10
#pragma unroll
            for (int j = 0; j < 20; ++j) {
                int c = j & 1, k = j >> 1;
                acc[j] = fmaf(w2, wc[c * 10 + k], acc[j]);
            }
            acc[20] = fmaf(w2, bconv[h], acc[20]);
        }
#pragma unroll
        for (int off = 16; off; off >>= 1) {
#pragma unroll
            for (int j = 0; j < 21; ++j)
                acc[j] += __shfl_xor_sync(0xffffffffu, acc[j], off);
        }
        if (lane == 0) {
#pragma unroll
            for (int j = 0; j < 20; ++j) g_Wf[e * 24 + j] = acc[j];
            g_Wf[e * 24 + 20] = W1[e * 2 + 0];
            g_Wf[e * 24 + 21] = W1[e * 2 + 1];
            g_Wf[e * 24 + 22] = 0.f;
            g_Wf[e * 24 + 23] = 0.f;
            g_bias[e] = acc[20] + b1[e] + b2[e];
        }
        return;
    }

    // ---- grid build for batch b ----
    int b = blk;
    const float2* xb = reinterpret_cast<const float2*>(x) + (size_t)b * NN;

    float2 p[4];
#pragma unroll
    for (int i = 0; i < 4; ++i) p[i] = xb[tid + 512 * i];

    // bbox reduction
    float mnx = p[0].x, mxx = p[0].x, mny = p[0].y, mxy = p[0].y;
#pragma unroll
    for (int i = 1; i < 4; ++i) {
        mnx = fminf(mnx, p[i].x); mxx = fmaxf(mxx, p[i].x);
        mny = fminf(mny, p[i].y); mxy = fmaxf(mxy, p[i].y);
    }
#pragma unroll
    for (int off = 16; off; off >>= 1) {
        mnx = fminf(mnx, __shfl_xor_sync(~0u, mnx, off));
        mxx = fmaxf(mxx, __shfl_xor_sync(~0u, mxx, off));
        mny = fminf(mny, __shfl_xor_sync(~0u, mny, off));
        mxy = fmaxf(mxy, __shfl_xor_sync(~0u, mxy, off));
    }
    if (lane == 0) { rmn[wid][0] = mnx; rmn[wid][1] = mny;
                     rmx[wid][0] = mxx; rmx[wid][1] = mxy; }
    __syncthreads();
    if (tid == 0) {
        float a = rmn[0][0], bx = rmx[0][0], c = rmn[0][1], d = rmx[0][1];
        for (int i = 1; i < 16; ++i) {
            a = fminf(a, rmn[i][0]); bx = fmaxf(bx, rmx[i][0]);
            c = fminf(c, rmn[i][1]); d = fmaxf(d, rmx[i][1]);
        }
        float ox = a - 1e-4f, oy = c - 1e-4f;
        float range = fmaxf(bx - a, d - c) + 2e-4f;
        float h = range / (float)G;
        float invh = 1.0f / h;
        s_info[0] = ox; s_info[1] = oy; s_info[2] = invh;
        g_gridInfo[b] = make_float4(ox, oy, invh, h);
    }
    for (int i = tid; i < GC; i += 512) hist[i] = 0;
    __syncthreads();

    float ox = s_info[0], oy = s_info[1], invh = s_info[2];
    int cell[4];
#pragma unroll
    for (int i = 0; i < 4; ++i) {
        int cx = (int)((p[i].x - ox) * invh); cx = max(0, min(G - 1, cx));
        int cy = (int)((p[i].y - oy) * invh); cy = max(0, min(G - 1, cy));
        cell[i] = cy * G + cx;
        atomicAdd(&hist[cell[i]], 1);
    }
    __syncthreads();

    // exclusive prefix sum over GC=1024 bins (2 per thread)
    int base = tid * 2;
    int v0 = hist[base], v1 = hist[base + 1];
    int s = v0 + v1;
    int inc = s;
#pragma unroll
    for (int off = 1; off < 32; off <<= 1) {
        int n = __shfl_up_sync(~0u, inc, off);
        if (lane >= off) inc += n;
    }
    if (lane == 31) wsum[wid] = inc;
    int wex = inc - s;
    __syncthreads();
    if (wid == 0) {
        int vv = (lane < 16) ? wsum[lane] : 0;
        int orig = vv;
#pragma unroll
        for (int off = 1; off < 16; off <<= 1) {
            int n = __shfl_up_sync(~0u, vv, off);
            if (lane >= off) vv += n;
        }
        if (lane < 16) wsum[lane] = vv - orig;
    }
    __syncthreads();
    int gbase = wsum[wid] + wex;
    g_cellStart[b][base]     = gbase;
    g_cellStart[b][base + 1] = gbase + v0;
    hist[base]     = gbase;          // becomes scatter cursor
    hist[base + 1] = gbase + v0;
    if (tid == 0) g_cellStart[b][GC] = NN;
    __syncthreads();

    // scatter (order within cell arbitrary; ties resolved by packed orig idx)
#pragma unroll
    for (int i = 0; i < 4; ++i) {
        int pos = atomicAdd(&hist[cell[i]], 1);
        float sq = __fadd_rn(__fmul_rn(p[i].x, p[i].x),
                             __fmul_rn(p[i].y, p[i].y));
        int orig = tid + 512 * i;
        g_sorted[b * NN + pos] =
            make_float4(p[i].x, p[i].y, sq, __int_as_float((orig << 11) | pos));
    }
}

// ---------------------------------------------------------------------------
// Main kernel (R12 structure — best measured): 2 threads per point, per-lane
// ring scan, branchless bubble insert, f32x2 epilogue. ONLY change vs R12:
// depth-1 software prefetch in evalRange — candidate i+1's LDS.128 issues
// before candidate i's compare/insert chain, hiding ~29 cyc LDS latency.
// Evaluation order and insert sequence unchanged => bit-identical output.
// Selection key = (bits(max(d2,0))<<32)|(orig<<11|pos) => exact stable argsort.
// ---------------------------------------------------------------------------
__global__ __launch_bounds__(TPB, 5)
void conv_embed_kernel(float* __restrict__ out) {
    extern __shared__ float smem[];
    float4* xs    = reinterpret_cast<float4*>(smem);          // [NN]   32 KB
    int*    cs    = reinterpret_cast<int*>(smem + NN * 4);    // [CSP]  4.1 KB
    float*  gs    = smem + NN * 4 + CSP;                      // [PPB*24] 6.1 KB
    int*    gorig = reinterpret_cast<int*>(gs + PPB * 24);    // [PPB]

    int b = blockIdx.y;
    int tid = threadIdx.x;

    // Phase 0: stage batch data
    const float4* srt = g_sorted + b * NN;
    for (int i = tid; i < NN; i += TPB) xs[i] = srt[i];
    for (int i = tid; i < GC + 1; i += TPB) cs[i] = g_cellStart[b][i];
    float4 gi = g_gridInfo[b];
    __syncthreads();

    // Phase 1: top-10 via ring expansion; lane pair (2i,2i+1) shares point i
    int half = tid & 1;
    int lp   = tid >> 1;                   // local point 0..63
    int sp   = blockIdx.x * PPB + lp;      // sorted position
    float4 me = xs[sp];
    float x0 = me.x, x1 = me.y, sqi = me.z;
    int mypacked = __float_as_int(me.w);

    int cx = (int)((x0 - gi.x) * gi.z); cx = max(0, min(G - 1, cx));
    int cy = (int)((x1 - gi.y) * gi.z); cy = max(0, min(G - 1, cy));
    float h = gi.w;

    unsigned long long lst[KK1];
#pragma unroll
    for (int s = 0; s < KK1; ++s) lst[s] = 0xFFFFFFFFFFFFFFFFULL;

    auto evalRange = [&](int q0, int q1) {
        int q = q0 + half;
        if (q >= q1) return;
        float4 c = xs[q];                          // first load
        q += 2;
        while (true) {
            bool more = (q < q1);
            float4 cn;
            if (more) cn = xs[q];                  // PREFETCH next candidate
            // process current (same order/rounding as R12)
            float dot = __fadd_rn(__fmul_rn(x0, c.x), __fmul_rn(x1, c.y));
            float d2  = __fmaf_rn(-2.0f, dot, __fadd_rn(sqi, c.z));
            d2 = fmaxf(d2, 0.0f);
            unsigned long long nk =
                ((unsigned long long)__float_as_uint(d2) << 32) |
                (unsigned)__float_as_int(c.w);
            if (nk < lst[KK1 - 1]) {
                lst[KK1 - 1] = nk;
#pragma unroll
                for (int s = KK1 - 1; s >= 1; --s) {   // branchless bubble
                    unsigned long long lo2 = lst[s] < lst[s - 1] ? lst[s] : lst[s - 1];
                    unsigned long long hi2 = lst[s] < lst[s - 1] ? lst[s - 1] : lst[s];
                    lst[s - 1] = lo2; lst[s] = hi2;
                }
            }
            if (!more) break;
            c = cn;
            q += 2;
        }
    };

    bool done = false;
    int r = 0;
    while (__ballot_sync(0xffffffffu, !done)) {
        int xlo = max(cx - r, 0), xhi = min(cx + r, G - 1);
        int ylo = max(cy - r, 0), yhi = min(cy + r, G - 1);
        if (!done) {
            for (int iy = ylo; iy <= yhi; ++iy) {
                int rowb = iy * G;
                if (r == 0 || iy == cy - r || iy == cy + r) {
                    evalRange(cs[rowb + xlo], cs[rowb + xhi + 1]);
                } else {
                    int cl = cx - r;
                    if (cl >= 0)      evalRange(cs[rowb + cl], cs[rowb + cl + 1]);
                    int cr2 = cx + r;
                    if (cr2 <= G - 1) evalRange(cs[rowb + cr2], cs[rowb + cr2 + 1]);
                }
            }
        }
        // pair-combined bound key: min of the two partial 10th keys
        // (valid upper bound on combined 10th; NaN-until-full -> fminf picks other)
        float k9  = __uint_as_float((unsigned)(lst[KK1 - 1] >> 32));
        float k9p = __shfl_xor_sync(0xffffffffu, k9, 1);
        float kmin = fminf(k9, k9p);
        if (!done) {
            bool full = (xlo == 0 && ylo == 0 && xhi == G - 1 && yhi == G - 1);
            float nb = (float)r * h;      // lower bound for rings >= r+1
            if (full || nb * nb > kmin + EPSM) done = true;  // NaN -> continue
            else ++r;
        }
    }

    // pair merge: pull partner's sorted-10, insert with early-out (exact u64)
    unsigned long long plst[KK1];
#pragma unroll
    for (int j = 0; j < KK1; ++j)
        plst[j] = __shfl_xor_sync(0xffffffffu, lst[j], 1);
#pragma unroll
    for (int j = 0; j < KK1; ++j) {
        if (plst[j] < lst[KK1 - 1]) {
            lst[KK1 - 1] = plst[j];
#pragma unroll
            for (int s = KK1 - 1; s >= 1; --s) {
                unsigned long long lo2 = lst[s] < lst[s - 1] ? lst[s] : lst[s - 1];
                unsigned long long hi2 = lst[s] < lst[s - 1] ? lst[s - 1] : lst[s];
                lst[s - 1] = lo2; lst[s] = hi2;
            }
        } else break;                      // partner ascending -> rest bigger
    }

    // Gather in ref order (descending distance, self last): rank 9-k.
    // Both pair threads hold identical merged lists; split the writes.
    float* g = gs + lp * 24;
#pragma unroll
    for (int k2 = 0; k2 < 5; ++k2) {
        int k = half * 5 + k2;
        int pk = (int)(lst[KK1 - 1 - k] & 0xFFFFFFFFULL);
        float4 cc = xs[pk & 0x7FF];
        g[2 * k]     = cc.x;
        g[2 * k + 1] = cc.y;
    }
    if (half == 0) {
        g[20] = x0; g[21] = x1; g[22] = 0.f; g[23] = 0.f;
        gorig[lp] = mypacked >> 11;
    }
    __syncthreads();

    // Phase 2: out[orig][e] = bias[e] + sum_t g[row][t] * Wf[e][t]
    // f32x2-packed: lanes accumulate the SAME per-lane FMA sequence as the
    // scalar version (acc0..acc3 interleave) => bit-identical result.
    int e = tid;                          // 128 threads = 128 channels
    const unsigned long long* wfp =
        reinterpret_cast<const unsigned long long*>(g_Wf + e * 24);
    unsigned long long wv[12];
#pragma unroll
    for (int j = 0; j < 12; ++j) wv[j] = wfp[j];
    float biasv = g_bias[e];

    size_t outbase = (size_t)b * NN;
#pragma unroll 2
    for (int row = 0; row < PPB; ++row) {
        const ulonglong2* gv = reinterpret_cast<const ulonglong2*>(gs + row * 24);
        ulonglong2 q0 = gv[0], q1 = gv[1], q2 = gv[2];
        ulonglong2 q3 = gv[3], q4 = gv[4], q5 = gv[5];
        unsigned long long acc01 = (unsigned long long)__float_as_uint(biasv);
        unsigned long long acc23 = 0ULL;
        FMA_F32X2(acc01, q0.x, wv[0]);   // floats 0,1   -> acc0,acc1
        FMA_F32X2(acc23, q0.y, wv[1]);   // floats 2,3   -> acc2,acc3
        FMA_F32X2(acc01, q1.x, wv[2]);
        FMA_F32X2(acc23, q1.y, wv[3]);
        FMA_F32X2(acc01, q2.x, wv[4]);
        FMA_F32X2(acc23, q2.y, wv[5]);
        FMA_F32X2(acc01, q3.x, wv[6]);
        FMA_F32X2(acc23, q3.y, wv[7]);
        FMA_F32X2(acc01, q4.x, wv[8]);
        FMA_F32X2(acc23, q4.y, wv[9]);
        FMA_F32X2(acc01, q5.x, wv[10]);
        FMA_F32X2(acc23, q5.y, wv[11]);
        float acc0 = __uint_as_float((unsigned)(acc01 & 0xFFFFFFFFULL));
        float acc1 = __uint_as_float((unsigned)(acc01 >> 32));
        float acc2 = __uint_as_float((unsigned)(acc23 & 0xFFFFFFFFULL));
        float acc3 = __uint_as_float((unsigned)(acc23 >> 32));
        out[(outbase + gorig[row]) * HH + e] = (acc0 + acc1) + (acc2 + acc3);
    }
}

extern "C" void kernel_launch(void* const* d_in, const int* in_sizes, int n_in,
                              void* d_out, int out_size) {
    const float* x     = (const float*)d_in[0];  // (16,2048,2)
    const float* Wconv = (const float*)d_in[1];  // (128,2,10)
    const float* bconv = (const float*)d_in[2];  // (128,)
    const float* W1    = (const float*)d_in[3];  // (128,2)
    const float* b1    = (const float*)d_in[4];  // (128,)
    const float* W2    = (const float*)d_in[5];  // (128,128)
    const float* b2    = (const float*)d_in[6];  // (128,)
    float* out = (float*)d_out;                  // (16,2048,128) fp32

    prep_kernel<<<BB + 8, 512>>>(x, Wconv, bconv, W1, b1, W2, b2);

    size_t smem_bytes = ((size_t)NN * 4 + CSP + (size_t)PPB * 24 + PPB) * 4;
    cudaFuncSetAttribute(conv_embed_kernel,
                         cudaFuncAttributeMaxDynamicSharedMemorySize,
                         (int)smem_bytes);
    dim3 grid(NN / PPB, BB);
    conv_embed_kernel<<<grid, TPB, smem_bytes>>>(out);
}

// round 16
// speedup vs baseline: 1.3980x; 1.0005x over previous
#include <cuda_runtime.h>

#define HH   128      // hidden dim
#define NN   2048     // points per batch
#define BB   16       // batches
#define KK1  10       // K+1 neighbors (incl. self)
#define TPB  128      // threads per block (search kernel)
#define PPB  64       // points per block = TPB/2 (2 threads per point)
#define G    32       // grid resolution per axis
#define GC   (G * G)
#define CSP  (GC + 4) // cellStart smem pad (keeps gs 16B-aligned)
#define EPSM 1e-4f    // bound margin >> max d2 rounding error (~1e-5)

// packed dual-FMA: two independent rn fp32 FMAs in one instruction (sm_10x)
#define FMA_F32X2(acc, a, w) \
    asm("fma.rn.f32x2 %0, %1, %2, %3;" : "=l"(acc) : "l"(a), "l"(w), "l"(acc))

// __device__ scratch (no cudaMalloc allowed)
__device__ __align__(16) float g_Wf[HH * 24];
__device__ float  g_bias[HH];
__device__ float4 g_sorted[BB * NN];        // (x, y, sq, packed) cell-sorted
__device__ int    g_cellStart[BB][GC + 1];
__device__ float4 g_gridInfo[BB];           // (ox, oy, invh, h)

// ---------------------------------------------------------------------------
// Prep kernel: blocks 0..15 build per-batch grid; blocks 16..23 fuse weights.
// ---------------------------------------------------------------------------
__global__ __launch_bounds__(512, 1)
void prep_kernel(const float* __restrict__ x,
                 const float* __restrict__ Wconv,
                 const float* __restrict__ bconv,
                 const float* __restrict__ W1,
                 const float* __restrict__ b1,
                 const float* __restrict__ W2,
                 const float* __restrict__ b2) {
    __shared__ int   hist[GC];
    __shared__ float rmn[16][2];
    __shared__ float rmx[16][2];
    __shared__ int   wsum[16];
    __shared__ float s_info[4];

    int blk = blockIdx.x, tid = threadIdx.x;
    int lane = tid & 31, wid = tid >> 5;

    if (blk >= BB) {
        // ---- weight fusion: warp per output channel e ----
        int e = (blk - BB) * 16 + wid;
        float acc[21];
#pragma unroll
        for (int j = 0; j < 21; ++j) acc[j] = 0.f;
        for (int h = lane; h < HH; h += 32) {
            float w2 = W2[e * HH + h];
            const float* wc = Wconv + h * 20;   // Wconv[h][c][k], c stride 10
#pragma unroll
            for (int j = 0; j < 20; ++j) {
                int c = j & 1, k = j >> 1;
                acc[j] = fmaf(w2, wc[c * 10 + k], acc[j]);
            }
            acc[20] = fmaf(w2, bconv[h], acc[20]);
        }
#pragma unroll
        for (int off = 16; off; off >>= 1) {
#pragma unroll
            for (int j = 0; j < 21; ++j)
                acc[j] += __shfl_xor_sync(0xffffffffu, acc[j], off);
        }
        if (lane == 0) {
#pragma unroll
            for (int j = 0; j < 20; ++j) g_Wf[e * 24 + j] = acc[j];
            g_Wf[e * 24 + 20] = W1[e * 2 + 0];
            g_Wf[e * 24 + 21] = W1[e * 2 + 1];
            g_Wf[e * 24 + 22] = 0.f;
            g_Wf[e * 24 + 23] = 0.f;
            g_bias[e] = acc[20] + b1[e] + b2[e];
        }
        return;
    }

    // ---- grid build for batch b ----
    int b = blk;
    const float2* xb = reinterpret_cast<const float2*>(x) + (size_t)b * NN;

    float2 p[4];
#pragma unroll
    for (int i = 0; i < 4; ++i) p[i] = xb[tid + 512 * i];

    // bbox reduction
    float mnx = p[0].x, mxx = p[0].x, mny = p[0].y, mxy = p[0].y;
#pragma unroll
    for (int i = 1; i < 4; ++i) {
        mnx = fminf(mnx, p[i].x); mxx = fmaxf(mxx, p[i].x);
        mny = fminf(mny, p[i].y); mxy = fmaxf(mxy, p[i].y);
    }
#pragma unroll
    for (int off = 16; off; off >>= 1) {
        mnx = fminf(mnx, __shfl_xor_sync(~0u, mnx, off));
        mxx = fmaxf(mxx, __shfl_xor_sync(~0u, mxx, off));
        mny = fminf(mny, __shfl_xor_sync(~0u, mny, off));
        mxy = fmaxf(mxy, __shfl_xor_sync(~0u, mxy, off));
    }
    if (lane == 0) { rmn[wid][0] = mnx; rmn[wid][1] = mny;
                     rmx[wid][0] = mxx; rmx[wid][1] = mxy; }
    __syncthreads();
    if (tid == 0) {
        float a = rmn[0][0], bx = rmx[0][0], c = rmn[0][1], d = rmx[0][1];
        for (int i = 1; i < 16; ++i) {
            a = fminf(a, rmn[i][0]); bx = fmaxf(bx, rmx[i][0]);
            c = fminf(c, rmn[i][1]); d = fmaxf(d, rmx[i][1]);
        }
        float ox = a - 1e-4f, oy = c - 1e-4f;
        float range = fmaxf(bx - a, d - c) + 2e-4f;
        float h = range / (float)G;
        float invh = 1.0f / h;
        s_info[0] = ox; s_info[1] = oy; s_info[2] = invh;
        g_gridInfo[b] = make_float4(ox, oy, invh, h);
    }
    for (int i = tid; i < GC; i += 512) hist[i] = 0;
    __syncthreads();

    float ox = s_info[0], oy = s_info[1], invh = s_info[2];
    int cell[4];
#pragma unroll
    for (int i = 0; i < 4; ++i) {
        int cx = (int)((p[i].x - ox) * invh); cx = max(0, min(G - 1, cx));
        int cy = (int)((p[i].y - oy) * invh); cy = max(0, min(G - 1, cy));
        cell[i] = cy * G + cx;
        atomicAdd(&hist[cell[i]], 1);
    }
    __syncthreads();

    // exclusive prefix sum over GC=1024 bins (2 per thread)
    int base = tid * 2;
    int v0 = hist[base], v1 = hist[base + 1];
    int s = v0 + v1;
    int inc = s;
#pragma unroll
    for (int off = 1; off < 32; off <<= 1) {
        int n = __shfl_up_sync(~0u, inc, off);
        if (lane >= off) inc += n;
    }
    if (lane == 31) wsum[wid] = inc;
    int wex = inc - s;
    __syncthreads();
    if (wid == 0) {
        int vv = (lane < 16) ? wsum[lane] : 0;
        int orig = vv;
#pragma unroll
        for (int off = 1; off < 16; off <<= 1) {
            int n = __shfl_up_sync(~0u, vv, off);
            if (lane >= off) vv += n;
        }
        if (lane < 16) wsum[lane] = vv - orig;
    }
    __syncthreads();
    int gbase = wsum[wid] + wex;
    g_cellStart[b][base]     = gbase;
    g_cellStart[b][base + 1] = gbase + v0;
    hist[base]     = gbase;          // becomes scatter cursor
    hist[base + 1] = gbase + v0;
    if (tid == 0) g_cellStart[b][GC] = NN;
    __syncthreads();

    // scatter (order within cell arbitrary; ties resolved by packed orig idx)
#pragma unroll
    for (int i = 0; i < 4; ++i) {
        int pos = atomicAdd(&hist[cell[i]], 1);
        float sq = __fadd_rn(__fmul_rn(p[i].x, p[i].x),
                             __fmul_rn(p[i].y, p[i].y));
        int orig = tid + 512 * i;
        g_sorted[b * NN + pos] =
            make_float4(p[i].x, p[i].y, sq, __int_as_float((orig << 11) | pos));
    }
}

// ---------------------------------------------------------------------------
// Main kernel (R15 base + minimal cell pruning): 2 threads per point.
// Own cell first; the 8 ring-1 cells each guarded by an exact rect-distance
// bound vs current k9 (skip is conservative: k9 only decreases, partial
// k9 >= combined k9, EPSM covers formula rounding, strict > on future
// inserts). evalRange itself unchanged (depth-1 prefetch, no internal gate).
// Ring loop from r=1 with EXACT wall-distance stop bound (dX + r*h).
// Candidate order changes but the top-10 set over unique u64 keys is order-
// independent and the list is sorted afterward => bit-identical output.
// Selection key = (bits(max(d2,0))<<32)|(orig<<11|pos) => exact stable argsort.
// ---------------------------------------------------------------------------
__global__ __launch_bounds__(TPB, 5)
void conv_embed_kernel(float* __restrict__ out) {
    extern __shared__ float smem[];
    float4* xs    = reinterpret_cast<float4*>(smem);          // [NN]   32 KB
    int*    cs    = reinterpret_cast<int*>(smem + NN * 4);    // [CSP]  4.1 KB
    float*  gs    = smem + NN * 4 + CSP;                      // [PPB*24] 6.1 KB
    int*    gorig = reinterpret_cast<int*>(gs + PPB * 24);    // [PPB]

    int b = blockIdx.y;
    int tid = threadIdx.x;

    // Phase 0: stage batch data
    const float4* srt = g_sorted + b * NN;
    for (int i = tid; i < NN; i += TPB) xs[i] = srt[i];
    for (int i = tid; i < GC + 1; i += TPB) cs[i] = g_cellStart[b][i];
    float4 gi = g_gridInfo[b];
    __syncthreads();

    // Phase 1: lane pair (2i,2i+1) shares point i (half-stride split)
    int half = tid & 1;
    int lp   = tid >> 1;                   // local point 0..63
    int sp   = blockIdx.x * PPB + lp;      // sorted position
    float4 me = xs[sp];
    float x0 = me.x, x1 = me.y, sqi = me.z;
    int mypacked = __float_as_int(me.w);

    float relx = x0 - gi.x;
    float rely = x1 - gi.y;
    int cx = (int)(relx * gi.z); cx = max(0, min(G - 1, cx));
    int cy = (int)(rely * gi.z); cy = max(0, min(G - 1, cy));
    float h = gi.w;

    unsigned long long lst[KK1];
#pragma unroll
    for (int s = 0; s < KK1; ++s) lst[s] = 0xFFFFFFFFFFFFFFFFULL;

    auto evalRange = [&](int q0, int q1) {
        int q = q0 + half;
        if (q >= q1) return;
        float4 c = xs[q];                          // first load
        q += 2;
        while (true) {
            bool more = (q < q1);
            float4 cn;
            if (more) cn = xs[q];                  // PREFETCH next candidate
            float dot = __fadd_rn(__fmul_rn(x0, c.x), __fmul_rn(x1, c.y));
            float d2  = __fmaf_rn(-2.0f, dot, __fadd_rn(sqi, c.z));
            d2 = fmaxf(d2, 0.0f);
            unsigned long long nk =
                ((unsigned long long)__float_as_uint(d2) << 32) |
                (unsigned)__float_as_int(c.w);
            if (nk < lst[KK1 - 1]) {
                lst[KK1 - 1] = nk;
#pragma unroll
                for (int s = KK1 - 1; s >= 1; --s) {   // branchless bubble
                    unsigned long long lo2 = lst[s] < lst[s - 1] ? lst[s] : lst[s - 1];
                    unsigned long long hi2 = lst[s] < lst[s - 1] ? lst[s - 1] : lst[s];
                    lst[s - 1] = lo2; lst[s] = hi2;
                }
            }
            if (!more) break;
            c = cn;
            q += 2;
        }
    };

    // own cell first (tightens k9 before ring-1 bound tests)
    evalRange(cs[cy * G + cx], cs[cy * G + cx + 1]);

    // wall distances of own cell (>= 0 for in-cell points)
    float dW = relx - (float)cx * h;
    float dE = (float)(cx + 1) * h - relx;
    float dS = rely - (float)cy * h;
    float dN = (float)(cy + 1) * h - rely;

    // ring-1: per-cell exact lower bound vs current k9 (NaN k9 -> scan)
    {
        auto tryc = [&](int ix, int iy, float b2) {
            if (ix >= 0 && ix < G && iy >= 0 && iy < G) {
                float k9 = __uint_as_float((unsigned)(lst[KK1 - 1] >> 32));
                if (!(b2 > k9 + EPSM)) {           // NaN -> scan
                    int rb = iy * G + ix;
                    evalRange(cs[rb], cs[rb + 1]);
                }
            }
        };
        tryc(cx - 1, cy,     dW * dW);
        tryc(cx + 1, cy,     dE * dE);
        tryc(cx,     cy - 1, dS * dS);
        tryc(cx,     cy + 1, dN * dN);
        tryc(cx - 1, cy - 1, dW * dW + dS * dS);
        tryc(cx + 1, cy - 1, dE * dE + dS * dS);
        tryc(cx - 1, cy + 1, dW * dW + dN * dN);
        tryc(cx + 1, cy + 1, dE * dE + dN * dN);
    }

    // rings >= 2: exact wall-distance stop bound, generic ring scan
    bool done = false;
    int r = 1;                             // rings 0..1 handled above
    while (__ballot_sync(0xffffffffu, !done)) {
        float k9  = __uint_as_float((unsigned)(lst[KK1 - 1] >> 32));
        float k9p = __shfl_xor_sync(0xffffffffu, k9, 1);
        float kmin = fminf(k9, k9p);       // >= true combined k9
        if (!done) {
            float rh = (float)r * h;
            float bl = (cx - r > 0)     ? dW + rh : 1e9f;
            float br = (cx + r < G - 1) ? dE + rh : 1e9f;
            float bb = (cy - r > 0)     ? dS + rh : 1e9f;
            float bt = (cy + r < G - 1) ? dN + rh : 1e9f;
            float bnd = fminf(fminf(bl, br), fminf(bb, bt));
            if (bnd >= 1e8f || bnd * bnd > kmin + EPSM) {  // NaN -> continue
                done = true;
            } else {
                ++r;
                int xlo = max(cx - r, 0), xhi = min(cx + r, G - 1);
                int yt = cy - r, yb = cy + r;
                if (yt >= 0)     evalRange(cs[yt * G + xlo], cs[yt * G + xhi + 1]);
                if (yb <= G - 1) evalRange(cs[yb * G + xlo], cs[yb * G + xhi + 1]);
                int y0 = max(yt + 1, 0), y1 = min(yb - 1, G - 1);
                int cl = cx - r, cr2 = cx + r;
                for (int iy = y0; iy <= y1; ++iy) {
                    if (cl >= 0)      evalRange(cs[iy * G + cl], cs[iy * G + cl + 1]);
                    if (cr2 <= G - 1) evalRange(cs[iy * G + cr2], cs[iy * G + cr2 + 1]);
                }
            }
        }
    }

    // pair merge: pull partner's sorted-10, insert with early-out (exact u64)
    unsigned long long plst[KK1];
#pragma unroll
    for (int j = 0; j < KK1; ++j)
        plst[j] = __shfl_xor_sync(0xffffffffu, lst[j], 1);
#pragma unroll
    for (int j = 0; j < KK1; ++j) {
        if (plst[j] < lst[KK1 - 1]) {
            lst[KK1 - 1] = plst[j];
#pragma unroll
            for (int s = KK1 - 1; s >= 1; --s) {
                unsigned long long lo2 = lst[s] < lst[s - 1] ? lst[s] : lst[s - 1];
                unsigned long long hi2 = lst[s] < lst[s - 1] ? lst[s - 1] : lst[s];
                lst[s - 1] = lo2; lst[s] = hi2;
            }
        } else break;                      // partner ascending -> rest bigger
    }

    // Gather in ref order (descending distance, self last): rank 9-k.
    // Both pair threads hold identical merged lists; split the writes.
    float* g = gs + lp * 24;
#pragma unroll
    for (int k2 = 0; k2 < 5; ++k2) {
        int k = half * 5 + k2;
        int pk = (int)(lst[KK1 - 1 - k] & 0xFFFFFFFFULL);
        float4 cc = xs[pk & 0x7FF];
        g[2 * k]     = cc.x;
        g[2 * k + 1] = cc.y;
    }
    if (half == 0) {
        g[20] = x0; g[21] = x1; g[22] = 0.f; g[23] = 0.f;
        gorig[lp] = mypacked >> 11;
    }
    __syncthreads();

    // Phase 2: out[orig][e] = bias[e] + sum_t g[row][t] * Wf[e][t]
    // f32x2-packed: lanes accumulate the SAME per-lane FMA sequence as the
    // scalar version (acc0..acc3 interleave) => bit-identical result.
    int e = tid;                          // 128 threads = 128 channels
    const unsigned long long* wfp =
        reinterpret_cast<const unsigned long long*>(g_Wf + e * 24);
    unsigned long long wv[12];
#pragma unroll
    for (int j = 0; j < 12; ++j) wv[j] = wfp[j];
    float biasv = g_bias[e];

    size_t outbase = (size_t)b * NN;
#pragma unroll 2
    for (int row = 0; row < PPB; ++row) {
        const ulonglong2* gv = reinterpret_cast<const ulonglong2*>(gs + row * 24);
        ulonglong2 q0 = gv[0], q1 = gv[1], q2 = gv[2];
        ulonglong2 q3 = gv[3], q4 = gv[4], q5 = gv[5];
        unsigned long long acc01 = (unsigned long long)__float_as_uint(biasv);
        unsigned long long acc23 = 0ULL;
        FMA_F32X2(acc01, q0.x, wv[0]);   // floats 0,1   -> acc0,acc1
        FMA_F32X2(acc23, q0.y, wv[1]);   // floats 2,3   -> acc2,acc3
        FMA_F32X2(acc01, q1.x, wv[2]);
        FMA_F32X2(acc23, q1.y, wv[3]);
        FMA_F32X2(acc01, q2.x, wv[4]);
        FMA_F32X2(acc23, q2.y, wv[5]);
        FMA_F32X2(acc01, q3.x, wv[6]);
        FMA_F32X2(acc23, q3.y, wv[7]);
        FMA_F32X2(acc01, q4.x, wv[8]);
        FMA_F32X2(acc23, q4.y, wv[9]);
        FMA_F32X2(acc01, q5.x, wv[10]);
        FMA_F32X2(acc23, q5.y, wv[11]);
        float acc0 = __uint_as_float((unsigned)(acc01 & 0xFFFFFFFFULL));
        float acc1 = __uint_as_float((unsigned)(acc01 >> 32));
        float acc2 = __uint_as_float((unsigned)(acc23 & 0xFFFFFFFFULL));
        float acc3 = __uint_as_float((unsigned)(acc23 >> 32));
        out[(outbase + gorig[row]) * HH + e] = (acc0 + acc1) + (acc2 + acc3);
    }
}

extern "C" void kernel_launch(void* const* d_in, const int* in_sizes, int n_in,
                              void* d_out, int out_size) {
    const float* x     = (const float*)d_in[0];  // (16,2048,2)
    const float* Wconv = (const float*)d_in[1];  // (128,2,10)
    const float* bconv = (const float*)d_in[2];  // (128,)
    const float* W1    = (const float*)d_in[3];  // (128,2)
    const float* b1    = (const float*)d_in[4];  // (128,)
    const float* W2    = (const float*)d_in[5];  // (128,128)
    const float* b2    = (const float*)d_in[6];  // (128,)
    float* out = (float*)d_out;                  // (16,2048,128) fp32

    prep_kernel<<<BB + 8, 512>>>(x, Wconv, bconv, W1, b1, W2, b2);

    size_t smem_bytes = ((size_t)NN * 4 + CSP + (size_t)PPB * 24 + PPB) * 4;
    cudaFuncSetAttribute(conv_embed_kernel,
                         cudaFuncAttributeMaxDynamicSharedMemorySize,
                         (int)smem_bytes);
    dim3 grid(NN / PPB, BB);
    conv_embed_kernel<<<grid, TPB, smem_bytes>>>(out);
}